// round 1
// baseline (speedup 1.0000x reference)
#include <cuda_runtime.h>

#define SS 8
#define NN 2048
#define KK 64
#define PI_F 3.14159265358979323846f

// ---------------- precomputed tables (written by precompute_kernel) ----------
__device__ float g_td[4][31];    // td table per type-pair
__device__ float g_base[4][64];  // td @ gw0[:31] + gb0
__device__ float g_v[64];        // gw0[31,:]

// ---------------- f32x2 packed helpers --------------------------------------
__device__ __forceinline__ unsigned long long pk2f(float lo, float hi) {
    unsigned long long r;
    asm("mov.b64 %0, {%1, %2};" : "=l"(r) : "f"(lo), "f"(hi));
    return r;
}
__device__ __forceinline__ unsigned long long fma2(unsigned long long a,
                                                   unsigned long long b,
                                                   unsigned long long c) {
    unsigned long long d;
    asm("fma.rn.f32x2 %0, %1, %2, %3;" : "=l"(d) : "l"(a), "l"(b), "l"(c));
    return d;
}
__device__ __forceinline__ unsigned long long add2(unsigned long long a,
                                                   unsigned long long b) {
    unsigned long long d;
    asm("add.rn.f32x2 %0, %1, %2;" : "=l"(d) : "l"(a), "l"(b));
    return d;
}
__device__ __forceinline__ float2 upk2(unsigned long long v) {
    float2 r;
    asm("mov.b64 {%0, %1}, %2;" : "=f"(r.x), "=f"(r.y) : "l"(v));
    return r;
}

// ---------------- tiny precompute: 4 type pairs through emb/f MLPs -----------
__global__ void precompute_kernel(const float* __restrict__ ew0, const float* __restrict__ eb0,
                                  const float* __restrict__ ew1, const float* __restrict__ eb1,
                                  const float* __restrict__ fw0, const float* __restrict__ fb0,
                                  const float* __restrict__ fw1, const float* __restrict__ fb1,
                                  const float* __restrict__ gw0, const float* __restrict__ gb0) {
    __shared__ float td_s[4][31];
    int t = threadIdx.x;
    if (t < 4) {
        float a = (float)(t >> 1);   // center type
        float b = (float)(t & 1);    // neighbor type
        float h32[32];
        for (int o = 0; o < 32; ++o) h32[o] = 0.f;
        for (int rev = 0; rev < 2; ++rev) {
            float x0 = rev ? b : a;
            float x1 = rev ? a : b;
            float h16[16];
            for (int i = 0; i < 16; ++i)
                h16[i] = fmaxf(x0 * ew0[i] + x1 * ew0[16 + i] + eb0[i], 0.f);
            for (int o = 0; o < 32; ++o) {
                float acc = eb1[o];
                for (int i = 0; i < 16; ++i) acc += h16[i] * ew1[i * 32 + o];
                h32[o] += fmaxf(acc, 0.f);
            }
        }
        float hf[32];
        for (int o = 0; o < 32; ++o) {
            float acc = fb0[o];
            for (int i = 0; i < 32; ++i) acc += h32[i] * fw0[i * 32 + o];
            hf[o] = fmaxf(acc, 0.f);
        }
        for (int o = 0; o < 31; ++o) {
            float acc = fb1[o];
            for (int i = 0; i < 32; ++i) acc += hf[i] * fw1[i * 31 + o];
            float td = fmaxf(acc, 0.f);
            td_s[t][o] = td;
            g_td[t][o] = td;
        }
    }
    __syncthreads();
    if (t < 64) {
        g_v[t] = gw0[31 * 64 + t];
        for (int p = 0; p < 4; ++p) {
            float acc = gb0[t];
            for (int i = 0; i < 31; ++i) acc += td_s[p][i] * gw0[i * 64 + t];
            g_base[p][t] = acc;
        }
    }
}

// ---------------- fused main kernel: one CTA per (s, n) ----------------------
__global__ __launch_bounds__(128)
void desc_kernel(const float* __restrict__ inputs,   // (S,N,3)
                 const int*   __restrict__ types,    // (S,N)
                 const int*   __restrict__ neigh,    // (S,N,K)
                 const float* __restrict__ length,   // (3,)
                 const float* __restrict__ gw1,      // (64,128)
                 const float* __restrict__ gb1,      // (128,)
                 float*       __restrict__ out)      // (S,N,128,16)
{
    __shared__ __align__(16) float  y1s[KK * 64];    // y1 rows per neighbor
    __shared__ __align__(16) float4 rts4[KK];        // r_tilde per neighbor
    __shared__ float base_s[4][64];
    __shared__ float v_s[64];
    __shared__ float td_s[4][32];                    // padded row
    __shared__ float sk_s[KK];
    __shared__ int   pk_s[KK];
    __shared__ __align__(16) float4 AsmF[16];

    const int e  = threadIdx.x;        // output channel 0..127
    const int sn = blockIdx.x;
    const int s  = sn >> 11;           // N = 2048
    const int n  = sn & (NN - 1);

    // weight column for this channel, packed into f32x2 pairs (64 regs)
    unsigned long long wcol2[32];
#pragma unroll
    for (int jp = 0; jp < 32; ++jp) {
        float wl = gw1[(2 * jp) * 128 + e];
        float wh = gw1[(2 * jp + 1) * 128 + e];
        wcol2[jp] = pk2f(wl, wh);
    }
    const float be = gb1[e];

    if (e < KK) {
        // geometry for neighbor k = e
        int k = e;
        int idx = neigh[(size_t)sn * KK + k];
        bool msk = idx < 0;
        int i0 = msk ? 0 : idx;
        float Lx = length[0], Ly = length[1], Lz = length[2];
        const float* pc = inputs + ((size_t)s * NN + n) * 3;
        const float* pn = inputs + ((size_t)s * NN + i0) * 3;
        float dx = pn[0] - pc[0];
        float dy = pn[1] - pc[1];
        float dz = pn[2] - pc[2];
        dx -= Lx * rintf(dx / Lx);
        dy -= Ly * rintf(dy / Ly);
        dz -= Lz * rintf(dz / Lz);
        float rsq = dx * dx + dy * dy + dz * dz;
        float r   = sqrtf(rsq > 0.f ? rsq : 1.0f);
        float inv = 1.0f / r;
        float sw;
        if (r < 6.0f)       sw = inv;
        else if (r < 12.0f) { float u = (r - 6.0f) * (1.0f / 6.0f);
                              sw = inv * (0.5f * cosf(PI_F * u) + 0.5f); }
        else                sw = 0.f;
        bool valid = (!msk) && (rsq > 0.f);
        float sij = valid ? sw : 0.f;
        float f   = sij * inv;
        rts4[k] = make_float4(sij, dx * f, dy * f, dz * f);
        sk_s[k] = sij;
        int ct = types[(size_t)s * NN + n];
        int nt = types[(size_t)s * NN + i0];
        pk_s[k] = ct * 2 + nt;
    } else {
        // meanwhile: stage precomputed tables into smem
        int t = e - 64;
        for (int i = t; i < 64; i += 64)      v_s[i] = g_v[i];
        for (int i = t; i < 4 * 64; i += 64)  ((float*)base_s)[i] = ((const float*)g_base)[i];
        for (int i = t; i < 4 * 31; i += 64)  td_s[i / 31][i % 31] = ((const float*)g_td)[i];
    }
    __syncthreads();

    // phase 2: y1[k][j] = relu(base[p] + s*v) + resnet tail, all 64x64 values
#pragma unroll
    for (int it = 0; it < 32; ++it) {
        int idx = e + it * 128;
        int k = idx >> 6, j = idx & 63;
        int p = pk_s[k];
        float sij = sk_s[k];
        float y = fmaxf(base_s[p][j] + sij * v_s[j], 0.f);
        int j32 = j & 31;
        float tail = (j32 < 31) ? td_s[p][j32] : sij;
        y1s[idx] = y + tail;
    }
    __syncthreads();

    // phase 3: per-k G[k,e] = relu(y1[k]@w_e + b_e) + y1[k][e&63];
    //          A[e,d] += G[k,e] * r_tilde[k,d]
    float A0 = 0.f, A1 = 0.f, A2 = 0.f, A3 = 0.f;
    const int etail = e & 63;
    for (int k = 0; k < KK; ++k) {
        const double2* yrow = (const double2*)(y1s + k * 64);
        unsigned long long a0 = pk2f(be, 0.f);   // fold bias into chain 0
        unsigned long long a1 = 0ull, a2 = 0ull, a3 = 0ull;
#pragma unroll
        for (int q = 0; q < 16; ++q) {
            double2 y2 = yrow[q];
            unsigned long long ylo = __double_as_longlong(y2.x);
            unsigned long long yhi = __double_as_longlong(y2.y);
            if ((q & 1) == 0) {
                a0 = fma2(ylo, wcol2[2 * q],     a0);
                a1 = fma2(yhi, wcol2[2 * q + 1], a1);
            } else {
                a2 = fma2(ylo, wcol2[2 * q],     a2);
                a3 = fma2(yhi, wcol2[2 * q + 1], a3);
            }
        }
        unsigned long long sAB = add2(add2(a0, a1), add2(a2, a3));
        float2 sf = upk2(sAB);
        float g = sf.x + sf.y;
        g = fmaxf(g, 0.f) + y1s[k * 64 + etail];
        float4 rt = rts4[k];
        A0 = fmaf(g, rt.x, A0);
        A1 = fmaf(g, rt.y, A1);
        A2 = fmaf(g, rt.z, A2);
        A3 = fmaf(g, rt.w, A3);
    }

    // phase 4: D[e,m] = sum_d A[e,d] * A[m,d]   (G2 = G[:, :16] => B = A[:16])
    if (e < 16) AsmF[e] = make_float4(A0, A1, A2, A3);
    __syncthreads();

    float* op = out + ((size_t)sn * 128 + e) * 16;
#pragma unroll
    for (int m4 = 0; m4 < 4; ++m4) {
        float4 o;
        {
            float4 am = AsmF[4 * m4 + 0];
            o.x = A0 * am.x + A1 * am.y + A2 * am.z + A3 * am.w;
        }
        {
            float4 am = AsmF[4 * m4 + 1];
            o.y = A0 * am.x + A1 * am.y + A2 * am.z + A3 * am.w;
        }
        {
            float4 am = AsmF[4 * m4 + 2];
            o.z = A0 * am.x + A1 * am.y + A2 * am.z + A3 * am.w;
        }
        {
            float4 am = AsmF[4 * m4 + 3];
            o.w = A0 * am.x + A1 * am.y + A2 * am.z + A3 * am.w;
        }
        ((float4*)op)[m4] = o;
    }
}

// ---------------- launch -----------------------------------------------------
extern "C" void kernel_launch(void* const* d_in, const int* in_sizes, int n_in,
                              void* d_out, int out_size) {
    const float* inputs = (const float*)d_in[0];
    const int*   types  = (const int*)d_in[1];
    const int*   neigh  = (const int*)d_in[2];
    const float* length = (const float*)d_in[3];
    const float* ew0 = (const float*)d_in[4];
    const float* eb0 = (const float*)d_in[5];
    const float* ew1 = (const float*)d_in[6];
    const float* eb1 = (const float*)d_in[7];
    const float* fw0 = (const float*)d_in[8];
    const float* fb0 = (const float*)d_in[9];
    const float* fw1 = (const float*)d_in[10];
    const float* fb1 = (const float*)d_in[11];
    const float* gw0 = (const float*)d_in[12];
    const float* gb0 = (const float*)d_in[13];
    const float* gw1 = (const float*)d_in[14];
    const float* gb1 = (const float*)d_in[15];

    precompute_kernel<<<1, 128>>>(ew0, eb0, ew1, eb1, fw0, fb0, fw1, fb1, gw0, gb0);
    desc_kernel<<<SS * NN, 128>>>(inputs, types, neigh, length, gw1, gb1, (float*)d_out);
}

// round 3
// speedup vs baseline: 2.0733x; 2.0733x over previous
#include <cuda_runtime.h>
#include <cuda_bf16.h>
#include <cstdint>

#define SS 8
#define NN 2048
#define KK 64
#define PI_F 3.14159265358979323846f

// ---------------- precomputed tables (written by precompute_kernel) ----------
__device__ float g_td[4][31];      // td table per type-pair
__device__ float g_base[4][64];    // td @ gw0[:31] + gb0
__device__ float g_v[64];          // gw0[31,:]
// W^T fragments in mma.sync B-register layout: [nt(16)][ks(4)][lane(32)] -> {b0,b1}
__device__ uint2 g_bfrag_hi[2048];
__device__ uint2 g_bfrag_lo[2048];

// ---------------- helpers ----------------------------------------------------
__device__ __forceinline__ uint32_t smem_u32(const void* p) {
    uint32_t a;
    asm("{ .reg .u64 t; cvta.to.shared.u64 t, %1; cvt.u32.u64 %0, t; }" : "=r"(a) : "l"(p));
    return a;
}
__device__ __forceinline__ void ldm4(uint32_t* r, uint32_t addr) {
    asm volatile("ldmatrix.sync.aligned.m8n8.x4.shared.b16 {%0,%1,%2,%3}, [%4];"
                 : "=r"(r[0]), "=r"(r[1]), "=r"(r[2]), "=r"(r[3]) : "r"(addr));
}
__device__ __forceinline__ void mma16816(float* c, const uint32_t* a, uint2 b) {
    asm volatile("mma.sync.aligned.m16n8k16.row.col.f32.bf16.bf16.f32 "
                 "{%0,%1,%2,%3}, {%4,%5,%6,%7}, {%8,%9}, {%0,%1,%2,%3};"
                 : "+f"(c[0]), "+f"(c[1]), "+f"(c[2]), "+f"(c[3])
                 : "r"(a[0]), "r"(a[1]), "r"(a[2]), "r"(a[3]), "r"(b.x), "r"(b.y));
}
__device__ __forceinline__ uint32_t pack_bf16x2(float lo, float hi) {
    __nv_bfloat16 l = __float2bfloat16(lo);
    __nv_bfloat16 h = __float2bfloat16(hi);
    return (uint32_t)__bfloat16_as_ushort(l) | ((uint32_t)__bfloat16_as_ushort(h) << 16);
}

// ---------------- tiny precompute: 4 type pairs + W fragment pack ------------
__global__ void precompute_kernel(const float* __restrict__ ew0, const float* __restrict__ eb0,
                                  const float* __restrict__ ew1, const float* __restrict__ eb1,
                                  const float* __restrict__ fw0, const float* __restrict__ fb0,
                                  const float* __restrict__ fw1, const float* __restrict__ fb1,
                                  const float* __restrict__ gw0, const float* __restrict__ gb0,
                                  const float* __restrict__ gw1) {
    __shared__ float td_s[4][31];
    int t = threadIdx.x;
    if (t < 4) {
        float a = (float)(t >> 1);
        float b = (float)(t & 1);
        float h32[32];
        for (int o = 0; o < 32; ++o) h32[o] = 0.f;
        for (int rev = 0; rev < 2; ++rev) {
            float x0 = rev ? b : a;
            float x1 = rev ? a : b;
            float h16[16];
            for (int i = 0; i < 16; ++i)
                h16[i] = fmaxf(x0 * ew0[i] + x1 * ew0[16 + i] + eb0[i], 0.f);
            for (int o = 0; o < 32; ++o) {
                float acc = eb1[o];
                for (int i = 0; i < 16; ++i) acc += h16[i] * ew1[i * 32 + o];
                h32[o] += fmaxf(acc, 0.f);
            }
        }
        float hf[32];
        for (int o = 0; o < 32; ++o) {
            float acc = fb0[o];
            for (int i = 0; i < 32; ++i) acc += h32[i] * fw0[i * 32 + o];
            hf[o] = fmaxf(acc, 0.f);
        }
        for (int o = 0; o < 31; ++o) {
            float acc = fb1[o];
            for (int i = 0; i < 32; ++i) acc += hf[i] * fw1[i * 31 + o];
            float td = fmaxf(acc, 0.f);
            td_s[t][o] = td;
            g_td[t][o] = td;
        }
    }
    __syncthreads();
    if (t < 64) {
        g_v[t] = gw0[31 * 64 + t];
        for (int p = 0; p < 4; ++p) {
            float acc = gb0[t];
            for (int i = 0; i < 31; ++i) acc += td_s[p][i] * gw0[i * 64 + t];
            g_base[p][t] = acc;
        }
    }
    // B fragments: B[k=j][n=e] = gw1[j*128+e], split hi/lo bf16,
    // mma.sync m16n8k16 layout: b0 = {B[j0][e], B[j0+1][e]}, b1 = {B[j0+8][e], B[j0+9][e]}
    // j0 = ks*16 + (lane%4)*2, e = nt*8 + lane/4
    for (int idx = t; idx < 2048; idx += 128) {
        int lane = idx & 31;
        int ks   = (idx >> 5) & 3;
        int nt   = idx >> 7;
        int e    = nt * 8 + (lane >> 2);
        int j0   = ks * 16 + (lane & 3) * 2;
        float w00 = gw1[j0 * 128 + e];
        float w01 = gw1[(j0 + 1) * 128 + e];
        float w10 = gw1[(j0 + 8) * 128 + e];
        float w11 = gw1[(j0 + 9) * 128 + e];
        float h00 = __bfloat162float(__float2bfloat16(w00));
        float h01 = __bfloat162float(__float2bfloat16(w01));
        float h10 = __bfloat162float(__float2bfloat16(w10));
        float h11 = __bfloat162float(__float2bfloat16(w11));
        g_bfrag_hi[idx] = make_uint2(pack_bf16x2(h00, h01), pack_bf16x2(h10, h11));
        g_bfrag_lo[idx] = make_uint2(pack_bf16x2(w00 - h00, w01 - h01),
                                     pack_bf16x2(w10 - h10, w11 - h11));
    }
}

// ---------------- fused main kernel: one CTA per 2 (s,n) pairs ---------------
__global__ __launch_bounds__(128)
void desc_kernel(const float* __restrict__ inputs,
                 const int*   __restrict__ types,
                 const int*   __restrict__ neigh,
                 const float* __restrict__ length,
                 const float* __restrict__ gb1,
                 float*       __restrict__ out)
{
    // Y panels: 128 rows x 64 bf16 (128B rows), 16B-chunk XOR swizzle (c ^= row&7)
    __shared__ __align__(128) unsigned char yhi[128 * 128];
    __shared__ __align__(128) unsigned char ylo[128 * 128];
    __shared__ __align__(16) float4 rts4[128];
    __shared__ float sk_s[128];
    __shared__ int   pk_s[128];
    __shared__ float base_s[4 * 64];
    __shared__ float v_s[64];
    __shared__ float td_s[4 * 32];
    __shared__ float b1_s[128];
    __shared__ __align__(16) float4 A_s[2][128];

    const int t    = threadIdx.x;
    const int w    = t >> 5;
    const int lane = t & 31;

    // ---- stage tables ----
    for (int i = t; i < 256; i += 128) base_s[i] = ((const float*)g_base)[i];
    if (t < 64) v_s[t] = g_v[t];
    for (int i = t; i < 124; i += 128) td_s[(i / 31) * 32 + (i % 31)] = ((const float*)g_td)[i];
    if (t < 4) td_s[t * 32 + 31] = 0.f;
    b1_s[t] = gb1[t];

    // ---- geometry for k-row t: sn_local = t>>6, k = t&63 ----
    const int sn = blockIdx.x * 2 + (t >> 6);
    const int s  = sn >> 11;
    const int n  = sn & (NN - 1);
    float sij; int pp;
    {
        int idx = neigh[(size_t)sn * KK + (t & 63)];
        bool msk = idx < 0;
        int i0 = msk ? 0 : idx;
        float Lx = length[0], Ly = length[1], Lz = length[2];
        const float* pc = inputs + ((size_t)s * NN + n) * 3;
        const float* pn = inputs + ((size_t)s * NN + i0) * 3;
        float dx = pn[0] - pc[0];
        float dy = pn[1] - pc[1];
        float dz = pn[2] - pc[2];
        dx -= Lx * rintf(dx / Lx);
        dy -= Ly * rintf(dy / Ly);
        dz -= Lz * rintf(dz / Lz);
        float rsq = dx * dx + dy * dy + dz * dz;
        float r   = sqrtf(rsq > 0.f ? rsq : 1.0f);
        float inv = 1.0f / r;
        float sw;
        if (r < 6.0f)       sw = inv;
        else if (r < 12.0f) { float u = (r - 6.0f) * (1.0f / 6.0f);
                              sw = inv * (0.5f * cosf(PI_F * u) + 0.5f); }
        else                sw = 0.f;
        bool valid = (!msk) && (rsq > 0.f);
        sij = valid ? sw : 0.f;
        float f = sij * inv;
        rts4[t] = make_float4(sij, dx * f, dy * f, dz * f);
        sk_s[t] = sij;
        int ct = types[(size_t)s * NN + n];
        int nt = types[(size_t)s * NN + i0];
        pp = ct * 2 + nt;
        pk_s[t] = pp;
    }
    __syncthreads();   // tables ready

    // ---- phase 2: y row t -> bf16 hi/lo, swizzled 16B-chunk stores ----
    {
        const int rx = t & 7;
#pragma unroll
        for (int c = 0; c < 8; ++c) {
            uint32_t wh[4], wl[4];
#pragma unroll
            for (int q = 0; q < 4; ++q) {
                int jp = c * 4 + q;
                int j0 = 2 * jp, j1 = 2 * jp + 1;
                float y0 = fmaxf(base_s[pp * 64 + j0] + sij * v_s[j0], 0.f);
                float y1 = fmaxf(base_s[pp * 64 + j1] + sij * v_s[j1], 0.f);
                int j032 = j0 & 31, j132 = j1 & 31;
                y0 += (j032 < 31) ? td_s[pp * 32 + j032] : sij;
                y1 += (j132 < 31) ? td_s[pp * 32 + j132] : sij;
                float h0 = __bfloat162float(__float2bfloat16(y0));
                float h1 = __bfloat162float(__float2bfloat16(y1));
                wh[q] = pack_bf16x2(h0, h1);
                wl[q] = pack_bf16x2(y0 - h0, y1 - h1);
            }
            int off = t * 128 + (c ^ rx) * 16;
            *(uint4*)(yhi + off) = make_uint4(wh[0], wh[1], wh[2], wh[3]);
            *(uint4*)(ylo + off) = make_uint4(wl[0], wl[1], wl[2], wl[3]);
        }
    }
    __syncthreads();

    const uint32_t yhi_b = smem_u32(yhi);
    const uint32_t ylo_b = smem_u32(ylo);

    // loop invariants for epilogue: per combo cc = ntl*2 + c
    int   jcv[4]; float vjv[4]; bool ltv[4];
#pragma unroll
    for (int cc = 0; cc < 4; ++cc) {
        int j = w * 16 + (cc >> 1) * 8 + (lane & 3) * 2 + (cc & 1);  // 0..63
        jcv[cc] = j;
        vjv[cc] = v_s[j];
        ltv[cc] = ((j & 31) < 31);
    }

    // ---- two passes over e-halves ----
#pragma unroll
    for (int pss = 0; pss < 2; ++pss) {
        // B fragment preload (L2)
        uint2 bhi[2][4], blo[2][4];
#pragma unroll
        for (int ntl = 0; ntl < 2; ++ntl)
#pragma unroll
            for (int ks = 0; ks < 4; ++ks) {
                int idx = (((pss * 8 + w * 2 + ntl) * 4) + ks) * 32 + lane;
                bhi[ntl][ks] = g_bfrag_hi[idx];
                blo[ntl][ks] = g_bfrag_lo[idx];
            }
        float b1v[4];
#pragma unroll
        for (int cc = 0; cc < 4; ++cc) b1v[cc] = b1_s[pss * 64 + jcv[cc]];

        float part[2][4][4];
#pragma unroll
        for (int h = 0; h < 2; ++h)
#pragma unroll
            for (int cc = 0; cc < 4; ++cc)
#pragma unroll
                for (int d = 0; d < 4; ++d) part[h][cc][d] = 0.f;

#pragma unroll
        for (int mt = 0; mt < 8; ++mt) {
            float acc[2][4] = {{0.f, 0.f, 0.f, 0.f}, {0.f, 0.f, 0.f, 0.f}};
            const int arow  = mt * 16 + (lane & 15);
            const int arx   = arow & 7;
            const uint32_t abase = arow * 128;
#pragma unroll
            for (int ks = 0; ks < 4; ++ks) {
                uint32_t ah[4], al[4];
                uint32_t choff = (uint32_t)(((ks * 2 + (lane >> 4)) ^ arx) * 16);
                ldm4(ah, yhi_b + abase + choff);
                ldm4(al, ylo_b + abase + choff);
#pragma unroll
                for (int ntl = 0; ntl < 2; ++ntl) {
                    mma16816(acc[ntl], ah, bhi[ntl][ks]);
                    mma16816(acc[ntl], ah, blo[ntl][ks]);
                    mma16816(acc[ntl], al, bhi[ntl][ks]);
                }
            }
            // epilogue for this m-tile
            const int r0 = mt * 16 + (lane >> 2);
            const int r1 = r0 + 8;
            const float4 q0 = rts4[r0];
            const float4 q1 = rts4[r1];
            const int   p0 = pk_s[r0], p1 = pk_s[r1];
            const float s0 = sk_s[r0], s1 = sk_s[r1];
            const int h = mt >> 2;
#pragma unroll
            for (int cc = 0; cc < 4; ++cc) {
                const int ntl = cc >> 1, c = cc & 1;
                const int j = jcv[cc];
                const int j32 = j & 31;
                float tail0 = fmaxf(fmaf(s0, vjv[cc], base_s[p0 * 64 + j]), 0.f)
                            + (ltv[cc] ? td_s[p0 * 32 + j32] : s0);
                float tail1 = fmaxf(fmaf(s1, vjv[cc], base_s[p1 * 64 + j]), 0.f)
                            + (ltv[cc] ? td_s[p1 * 32 + j32] : s1);
                float g0 = fmaxf(acc[ntl][c]     + b1v[cc], 0.f) + tail0;
                float g1 = fmaxf(acc[ntl][2 + c] + b1v[cc], 0.f) + tail1;
                part[h][cc][0] = fmaf(g0, q0.x, fmaf(g1, q1.x, part[h][cc][0]));
                part[h][cc][1] = fmaf(g0, q0.y, fmaf(g1, q1.y, part[h][cc][1]));
                part[h][cc][2] = fmaf(g0, q0.z, fmaf(g1, q1.z, part[h][cc][2]));
                part[h][cc][3] = fmaf(g0, q0.w, fmaf(g1, q1.w, part[h][cc][3]));
            }
        }

        // reduce across the 8 lane-groups (lanes sharing lane&3): xor 4, 8, 16
#pragma unroll
        for (int h = 0; h < 2; ++h)
#pragma unroll
            for (int cc = 0; cc < 4; ++cc)
#pragma unroll
                for (int d = 0; d < 4; ++d) {
                    float v = part[h][cc][d];
                    v += __shfl_xor_sync(0xffffffffu, v, 4);
                    v += __shfl_xor_sync(0xffffffffu, v, 8);
                    v += __shfl_xor_sync(0xffffffffu, v, 16);
                    part[h][cc][d] = v;
                }
        if (lane < 4) {
#pragma unroll
            for (int h = 0; h < 2; ++h)
#pragma unroll
                for (int cc = 0; cc < 4; ++cc) {
                    int e = pss * 64 + w * 16 + (cc >> 1) * 8 + lane * 2 + (cc & 1);
                    A_s[h][e] = make_float4(part[h][cc][0], part[h][cc][1],
                                            part[h][cc][2], part[h][cc][3]);
                }
        }
    }
    __syncthreads();

    // ---- D[e,m] = sum_d A[e,d] * A[m,d] per sn-half ----
    const int e = t;
#pragma unroll
    for (int h = 0; h < 2; ++h) {
        float4 a = A_s[h][e];
        size_t gsn = (size_t)blockIdx.x * 2 + h;
        float4* op = (float4*)(out + (gsn * 128 + e) * 16);
#pragma unroll
        for (int m4 = 0; m4 < 4; ++m4) {
            float4 b0 = A_s[h][4 * m4 + 0];
            float4 b1 = A_s[h][4 * m4 + 1];
            float4 b2 = A_s[h][4 * m4 + 2];
            float4 b3 = A_s[h][4 * m4 + 3];
            float4 o;
            o.x = a.x * b0.x + a.y * b0.y + a.z * b0.z + a.w * b0.w;
            o.y = a.x * b1.x + a.y * b1.y + a.z * b1.z + a.w * b1.w;
            o.z = a.x * b2.x + a.y * b2.y + a.z * b2.z + a.w * b2.w;
            o.w = a.x * b3.x + a.y * b3.y + a.z * b3.z + a.w * b3.w;
            op[m4] = o;
        }
    }
}

// ---------------- launch -----------------------------------------------------
extern "C" void kernel_launch(void* const* d_in, const int* in_sizes, int n_in,
                              void* d_out, int out_size) {
    const float* inputs = (const float*)d_in[0];
    const int*   types  = (const int*)d_in[1];
    const int*   neigh  = (const int*)d_in[2];
    const float* length = (const float*)d_in[3];
    const float* ew0 = (const float*)d_in[4];
    const float* eb0 = (const float*)d_in[5];
    const float* ew1 = (const float*)d_in[6];
    const float* eb1 = (const float*)d_in[7];
    const float* fw0 = (const float*)d_in[8];
    const float* fb0 = (const float*)d_in[9];
    const float* fw1 = (const float*)d_in[10];
    const float* fb1 = (const float*)d_in[11];
    const float* gw0 = (const float*)d_in[12];
    const float* gb0 = (const float*)d_in[13];
    const float* gw1 = (const float*)d_in[14];
    const float* gb1 = (const float*)d_in[15];

    precompute_kernel<<<1, 128>>>(ew0, eb0, ew1, eb1, fw0, fb0, fw1, fb1, gw0, gb0, gw1);
    desc_kernel<<<SS * NN / 2, 128>>>(inputs, types, neigh, length, gb1, (float*)d_out);
}

// round 4
// speedup vs baseline: 2.2591x; 1.0896x over previous
#include <cuda_runtime.h>
#include <cuda_bf16.h>
#include <cstdint>

#define SS 8
#define NN 2048
#define KK 64
#define PI_F 3.14159265358979323846f

// ---------------- precomputed tables (written by precompute_kernel) ----------
__device__ float g_td[4][31];      // td table per type-pair
__device__ float g_base[4][64];    // td @ gw0[:31] + gb0
__device__ float g_v[64];          // gw0[31,:]
// W^T fragments in mma.sync B-register layout: [nt(16)][ks(4)][lane(32)] -> {b0,b1}
__device__ uint2 g_bfrag_hi[2048];
__device__ uint2 g_bfrag_lo[2048];

// ---------------- helpers ----------------------------------------------------
__device__ __forceinline__ uint32_t smem_u32(const void* p) {
    uint32_t a;
    asm("{ .reg .u64 t; cvta.to.shared.u64 t, %1; cvt.u32.u64 %0, t; }" : "=r"(a) : "l"(p));
    return a;
}
__device__ __forceinline__ void ldm4(uint32_t* r, uint32_t addr) {
    asm volatile("ldmatrix.sync.aligned.m8n8.x4.shared.b16 {%0,%1,%2,%3}, [%4];"
                 : "=r"(r[0]), "=r"(r[1]), "=r"(r[2]), "=r"(r[3]) : "r"(addr));
}
__device__ __forceinline__ void mma16816(float* c, const uint32_t* a, uint2 b) {
    asm volatile("mma.sync.aligned.m16n8k16.row.col.f32.bf16.bf16.f32 "
                 "{%0,%1,%2,%3}, {%4,%5,%6,%7}, {%8,%9}, {%0,%1,%2,%3};"
                 : "+f"(c[0]), "+f"(c[1]), "+f"(c[2]), "+f"(c[3])
                 : "r"(a[0]), "r"(a[1]), "r"(a[2]), "r"(a[3]), "r"(b.x), "r"(b.y));
}
__device__ __forceinline__ uint32_t pack_bf16x2(float lo, float hi) {
    __nv_bfloat16 l = __float2bfloat16(lo);
    __nv_bfloat16 h = __float2bfloat16(hi);
    return (uint32_t)__bfloat16_as_ushort(l) | ((uint32_t)__bfloat16_as_ushort(h) << 16);
}

// ---------------- tiny precompute: 4 type pairs + W fragment pack ------------
__global__ void precompute_kernel(const float* __restrict__ ew0, const float* __restrict__ eb0,
                                  const float* __restrict__ ew1, const float* __restrict__ eb1,
                                  const float* __restrict__ fw0, const float* __restrict__ fb0,
                                  const float* __restrict__ fw1, const float* __restrict__ fb1,
                                  const float* __restrict__ gw0, const float* __restrict__ gb0,
                                  const float* __restrict__ gw1) {
    __shared__ float td_s[4][31];
    int t = threadIdx.x;
    if (t < 4) {
        float a = (float)(t >> 1);
        float b = (float)(t & 1);
        float h32[32];
        for (int o = 0; o < 32; ++o) h32[o] = 0.f;
        for (int rev = 0; rev < 2; ++rev) {
            float x0 = rev ? b : a;
            float x1 = rev ? a : b;
            float h16[16];
            for (int i = 0; i < 16; ++i)
                h16[i] = fmaxf(x0 * ew0[i] + x1 * ew0[16 + i] + eb0[i], 0.f);
            for (int o = 0; o < 32; ++o) {
                float acc = eb1[o];
                for (int i = 0; i < 16; ++i) acc += h16[i] * ew1[i * 32 + o];
                h32[o] += fmaxf(acc, 0.f);
            }
        }
        float hf[32];
        for (int o = 0; o < 32; ++o) {
            float acc = fb0[o];
            for (int i = 0; i < 32; ++i) acc += h32[i] * fw0[i * 32 + o];
            hf[o] = fmaxf(acc, 0.f);
        }
        for (int o = 0; o < 31; ++o) {
            float acc = fb1[o];
            for (int i = 0; i < 32; ++i) acc += hf[i] * fw1[i * 31 + o];
            float td = fmaxf(acc, 0.f);
            td_s[t][o] = td;
            g_td[t][o] = td;
        }
    }
    __syncthreads();
    if (t < 64) {
        g_v[t] = gw0[31 * 64 + t];
        for (int p = 0; p < 4; ++p) {
            float acc = gb0[t];
            for (int i = 0; i < 31; ++i) acc += td_s[p][i] * gw0[i * 64 + t];
            g_base[p][t] = acc;
        }
    }
    // B fragments: mma.sync m16n8k16 col-major B layout
    for (int idx = t; idx < 2048; idx += 128) {
        int lane = idx & 31;
        int ks   = (idx >> 5) & 3;
        int nt   = idx >> 7;
        int e    = nt * 8 + (lane >> 2);
        int j0   = ks * 16 + (lane & 3) * 2;
        float w00 = gw1[j0 * 128 + e];
        float w01 = gw1[(j0 + 1) * 128 + e];
        float w10 = gw1[(j0 + 8) * 128 + e];
        float w11 = gw1[(j0 + 9) * 128 + e];
        float h00 = __bfloat162float(__float2bfloat16(w00));
        float h01 = __bfloat162float(__float2bfloat16(w01));
        float h10 = __bfloat162float(__float2bfloat16(w10));
        float h11 = __bfloat162float(__float2bfloat16(w11));
        g_bfrag_hi[idx] = make_uint2(pack_bf16x2(h00, h01), pack_bf16x2(h10, h11));
        g_bfrag_lo[idx] = make_uint2(pack_bf16x2(w00 - h00, w01 - h01),
                                     pack_bf16x2(w10 - h10, w11 - h11));
    }
}

// ---------------- fused main kernel: one CTA per 2 (s,n) pairs ---------------
__global__ __launch_bounds__(128, 3)
void desc_kernel(const float* __restrict__ inputs,
                 const int*   __restrict__ types,
                 const int*   __restrict__ neigh,
                 const float* __restrict__ length,
                 const float* __restrict__ gb1,
                 float*       __restrict__ out)
{
    // Y panels: 128 rows x 64 bf16 (128B rows), 16B-chunk XOR swizzle (c ^= row&7)
    __shared__ __align__(128) unsigned char yhi[128 * 128];
    __shared__ __align__(128) unsigned char ylo[128 * 128];
    __shared__ __align__(16) float4 rts4[128];
    __shared__ int   pk_s[128];
    __shared__ float base_s[4 * 68];   // padded stride 68 -> bank=(4p+j)%32
    __shared__ float v_s[64];
    __shared__ float td_s[4 * 33];     // padded stride 33 -> bank=(p+j)%32
    __shared__ float b1_s[128];
    __shared__ __align__(16) float4 A_s[2][128];

    const int t    = threadIdx.x;
    const int w    = t >> 5;
    const int lane = t & 31;

    // ---- B fragment preload first (hide L2 latency behind phase 1/2) ----
    uint2 bhi[4][4], blo[4][4];
#pragma unroll
    for (int ntl = 0; ntl < 4; ++ntl)
#pragma unroll
        for (int ks = 0; ks < 4; ++ks) {
            int idx = (((w * 4 + ntl) * 4) + ks) * 32 + lane;
            bhi[ntl][ks] = g_bfrag_hi[idx];
            blo[ntl][ks] = g_bfrag_lo[idx];
        }

    // ---- stage tables (padded strides) ----
    for (int i = t; i < 256; i += 128) base_s[(i >> 6) * 68 + (i & 63)] = ((const float*)g_base)[i];
    if (t < 64) v_s[t] = g_v[t];
    for (int i = t; i < 124; i += 128) td_s[(i / 31) * 33 + (i % 31)] = ((const float*)g_td)[i];
    if (t < 4) { td_s[t * 33 + 31] = 0.f; td_s[t * 33 + 32] = 0.f; }
    b1_s[t] = gb1[t];

    // ---- geometry for k-row t: sn_local = t>>6, k = t&63 ----
    const int sn = blockIdx.x * 2 + (t >> 6);
    const int s  = sn >> 11;
    const int n  = sn & (NN - 1);
    float sij; int pp;
    {
        int idx = neigh[(size_t)sn * KK + (t & 63)];
        bool msk = idx < 0;
        int i0 = msk ? 0 : idx;
        float Lx = length[0], Ly = length[1], Lz = length[2];
        const float* pc = inputs + ((size_t)s * NN + n) * 3;
        const float* pn = inputs + ((size_t)s * NN + i0) * 3;
        float dx = pn[0] - pc[0];
        float dy = pn[1] - pc[1];
        float dz = pn[2] - pc[2];
        dx -= Lx * rintf(dx / Lx);
        dy -= Ly * rintf(dy / Ly);
        dz -= Lz * rintf(dz / Lz);
        float rsq = dx * dx + dy * dy + dz * dz;
        float r   = sqrtf(rsq > 0.f ? rsq : 1.0f);
        float inv = 1.0f / r;
        float sw;
        if (r < 6.0f)       sw = inv;
        else if (r < 12.0f) { float u = (r - 6.0f) * (1.0f / 6.0f);
                              sw = inv * (0.5f * cosf(PI_F * u) + 0.5f); }
        else                sw = 0.f;
        bool valid = (!msk) && (rsq > 0.f);
        sij = valid ? sw : 0.f;
        float f = sij * inv;
        rts4[t] = make_float4(sij, dx * f, dy * f, dz * f);
        int ct = types[(size_t)s * NN + n];
        int nt = types[(size_t)s * NN + i0];
        pp = ct * 2 + nt;
        pk_s[t] = pp;
    }
    __syncthreads();   // tables ready

    // ---- phase 2: y row t -> bf16 hi/lo, swizzled 16B-chunk stores ----
    {
        const int rx = t & 7;
#pragma unroll
        for (int c = 0; c < 8; ++c) {
            uint32_t wh[4], wl[4];
#pragma unroll
            for (int q = 0; q < 4; ++q) {
                int jp = c * 4 + q;
                int j0 = 2 * jp, j1 = 2 * jp + 1;
                float y0 = fmaxf(base_s[pp * 68 + j0] + sij * v_s[j0], 0.f);
                float y1 = fmaxf(base_s[pp * 68 + j1] + sij * v_s[j1], 0.f);
                int j032 = j0 & 31, j132 = j1 & 31;
                y0 += (j032 < 31) ? td_s[pp * 33 + j032] : sij;
                y1 += (j132 < 31) ? td_s[pp * 33 + j132] : sij;
                float h0 = __bfloat162float(__float2bfloat16(y0));
                float h1 = __bfloat162float(__float2bfloat16(y1));
                wh[q] = pack_bf16x2(h0, h1);
                wl[q] = pack_bf16x2(y0 - h0, y1 - h1);
            }
            int off = t * 128 + (c ^ rx) * 16;
            *(uint4*)(yhi + off) = make_uint4(wh[0], wh[1], wh[2], wh[3]);
            *(uint4*)(ylo + off) = make_uint4(wl[0], wl[1], wl[2], wl[3]);
        }
    }
    __syncthreads();

    const uint32_t yhi_b = smem_u32(yhi);
    const uint32_t ylo_b = smem_u32(ylo);

    // per-cc loop invariants: cc = ntl*2 + c; e = w*32 + ntl*8 + (lane&3)*2 + c
    float vj[8], b1v[8];
#pragma unroll
    for (int cc = 0; cc < 8; ++cc) {
        int e = w * 32 + (cc >> 1) * 8 + (lane & 3) * 2 + (cc & 1);
        vj[cc]  = v_s[e & 63];
        b1v[cc] = b1_s[e];
    }
    const int jb = (w & 1) * 32 + (lane & 3) * 2;   // j = jb + ntl*8 + c  (mod 64 handled by w&1)

    // ---- single pass: full e range per warp, A loaded once per (mt,ks) ----
#pragma unroll
    for (int h = 0; h < 2; ++h) {
        float part[8][4];
#pragma unroll
        for (int cc = 0; cc < 8; ++cc)
#pragma unroll
            for (int d = 0; d < 4; ++d) part[cc][d] = 0.f;

#pragma unroll
        for (int mtl = 0; mtl < 4; ++mtl) {
            const int mt = h * 4 + mtl;
            float acc[4][4];
#pragma unroll
            for (int ntl = 0; ntl < 4; ++ntl)
#pragma unroll
                for (int d = 0; d < 4; ++d) acc[ntl][d] = 0.f;

            const int arow  = mt * 16 + (lane & 15);
            const int arx   = arow & 7;
            const uint32_t abase = (uint32_t)(arow * 128);
#pragma unroll
            for (int ks = 0; ks < 4; ++ks) {
                uint32_t ah[4], al[4];
                uint32_t choff = (uint32_t)(((ks * 2 + (lane >> 4)) ^ arx) * 16);
                ldm4(ah, yhi_b + abase + choff);
                ldm4(al, ylo_b + abase + choff);
#pragma unroll
                for (int ntl = 0; ntl < 4; ++ntl) {
                    mma16816(acc[ntl], ah, bhi[ntl][ks]);
                    mma16816(acc[ntl], ah, blo[ntl][ks]);
                    mma16816(acc[ntl], al, bhi[ntl][ks]);
                }
            }
            // epilogue for this m-tile
            const int r0 = mt * 16 + (lane >> 2);
            const int r1 = r0 + 8;
            const float4 q0 = rts4[r0];
            const float4 q1 = rts4[r1];
            const int   p0 = pk_s[r0], p1 = pk_s[r1];
            const float s0 = q0.x,     s1 = q1.x;
#pragma unroll
            for (int cc = 0; cc < 8; ++cc) {
                const int ntl = cc >> 1, c = cc & 1;
                const int j   = (jb + ntl * 8 + c) & 63;
                const int j32 = j & 31;
                const bool lt = (j32 < 31);
                float tail0 = fmaxf(fmaf(s0, vj[cc], base_s[p0 * 68 + j]), 0.f)
                            + (lt ? td_s[p0 * 33 + j32] : s0);
                float tail1 = fmaxf(fmaf(s1, vj[cc], base_s[p1 * 68 + j]), 0.f)
                            + (lt ? td_s[p1 * 33 + j32] : s1);
                float g0 = fmaxf(acc[ntl][c]     + b1v[cc], 0.f) + tail0;
                float g1 = fmaxf(acc[ntl][2 + c] + b1v[cc], 0.f) + tail1;
                part[cc][0] = fmaf(g0, q0.x, fmaf(g1, q1.x, part[cc][0]));
                part[cc][1] = fmaf(g0, q0.y, fmaf(g1, q1.y, part[cc][1]));
                part[cc][2] = fmaf(g0, q0.z, fmaf(g1, q1.z, part[cc][2]));
                part[cc][3] = fmaf(g0, q0.w, fmaf(g1, q1.w, part[cc][3]));
            }
        }

        // reduce across lane-groups sharing (lane&3): xor 4, 8, 16
#pragma unroll
        for (int cc = 0; cc < 8; ++cc)
#pragma unroll
            for (int d = 0; d < 4; ++d) {
                float v = part[cc][d];
                v += __shfl_xor_sync(0xffffffffu, v, 4);
                v += __shfl_xor_sync(0xffffffffu, v, 8);
                v += __shfl_xor_sync(0xffffffffu, v, 16);
                part[cc][d] = v;
            }
        if (lane < 4) {
#pragma unroll
            for (int cc = 0; cc < 8; ++cc) {
                int e = w * 32 + (cc >> 1) * 8 + lane * 2 + (cc & 1);
                A_s[h][e] = make_float4(part[cc][0], part[cc][1], part[cc][2], part[cc][3]);
            }
        }
    }
    __syncthreads();

    // ---- D[e,m] = sum_d A[e,d] * A[m,d] per sn-half ----
    const int e = t;
#pragma unroll
    for (int h = 0; h < 2; ++h) {
        float4 a = A_s[h][e];
        size_t gsn = (size_t)blockIdx.x * 2 + h;
        float4* op = (float4*)(out + (gsn * 128 + e) * 16);
#pragma unroll
        for (int m4 = 0; m4 < 4; ++m4) {
            float4 b0 = A_s[h][4 * m4 + 0];
            float4 b1 = A_s[h][4 * m4 + 1];
            float4 b2 = A_s[h][4 * m4 + 2];
            float4 b3 = A_s[h][4 * m4 + 3];
            float4 o;
            o.x = a.x * b0.x + a.y * b0.y + a.z * b0.z + a.w * b0.w;
            o.y = a.x * b1.x + a.y * b1.y + a.z * b1.z + a.w * b1.w;
            o.z = a.x * b2.x + a.y * b2.y + a.z * b2.z + a.w * b2.w;
            o.w = a.x * b3.x + a.y * b3.y + a.z * b3.z + a.w * b3.w;
            op[m4] = o;
        }
    }
}

// ---------------- launch -----------------------------------------------------
extern "C" void kernel_launch(void* const* d_in, const int* in_sizes, int n_in,
                              void* d_out, int out_size) {
    const float* inputs = (const float*)d_in[0];
    const int*   types  = (const int*)d_in[1];
    const int*   neigh  = (const int*)d_in[2];
    const float* length = (const float*)d_in[3];
    const float* ew0 = (const float*)d_in[4];
    const float* eb0 = (const float*)d_in[5];
    const float* ew1 = (const float*)d_in[6];
    const float* eb1 = (const float*)d_in[7];
    const float* fw0 = (const float*)d_in[8];
    const float* fb0 = (const float*)d_in[9];
    const float* fw1 = (const float*)d_in[10];
    const float* fb1 = (const float*)d_in[11];
    const float* gw0 = (const float*)d_in[12];
    const float* gb0 = (const float*)d_in[13];
    const float* gw1 = (const float*)d_in[14];
    const float* gb1 = (const float*)d_in[15];

    precompute_kernel<<<1, 128>>>(ew0, eb0, ew1, eb1, fw0, fb0, fw1, fb1, gw0, gb0, gw1);
    desc_kernel<<<SS * NN / 2, 128>>>(inputs, types, neigh, length, gb1, (float*)d_out);
}